// round 3
// baseline (speedup 1.0000x reference)
#include <cuda_runtime.h>
#include <math.h>

// Problem constants
#define B_  2
#define S_  4096
#define H_  2048
#define R_  2048
#define NB_ 16
#define BW_ 128
#define CW_ 4
#define M_  (B_*S_)        // 8192 rows (b,s flattened)
#define NCHUNK 16
#define CHL (S_/NCHUNK)    // 256
#define NCH (B_*R_)        // 4096 scan channels

// ---------------- scratch (device globals; no allocations allowed) ----------
__device__ float g_xr[(size_t)M_*R_];   // recurrent branch pre-conv
__device__ float g_gy[(size_t)M_*R_];   // gelu(y)
__device__ float g_xc[(size_t)M_*R_];   // conv output
__device__ float g_av[(size_t)M_*R_];   // a_t
__device__ float g_nx[(size_t)M_*R_];   // norm_x_t
__device__ float g_hg[(size_t)M_*R_];   // h * gelu(y)
__device__ float g_Asum[NCH*NCHUNK];
__device__ float g_Bsum[NCH*NCHUNK];
__device__ float g_carry[NCH*NCHUNK];

// ============================================================================
// SGEMM core (TN): C[m,n] = sum_k A[m,k]*B[n,k]
// A row-major [M,K], B row-major [N,K]. 128x128x16 tile, 256 thr, 8x8/thread.
// The accumulate + epilogue are expressed via a functor-style template so each
// use references device globals directly (no host symbol lookups needed).
// ============================================================================

template <int EPI>
__device__ __forceinline__ void sgemm_body(
    const float* __restrict__ A, const float* __restrict__ B,
    float* __restrict__ Cout, int K)
{
    __shared__ __align__(16) float As[16][128];
    __shared__ __align__(16) float Bs[16][128];

    const int tid = threadIdx.x;
    const int bm = blockIdx.y * 128;
    const int bn = blockIdx.x * 128;
    const int tx = tid & 15, ty = tid >> 4;
    const int lr = tid >> 2, lc = (tid & 3) << 2;

    float acc[8][8];
#pragma unroll
    for (int i = 0; i < 8; i++)
#pragma unroll
        for (int j = 0; j < 8; j++) acc[i][j] = 0.f;

    for (int k0 = 0; k0 < K; k0 += 16) {
        float4 a0 = *(const float4*)(A + (size_t)(bm + lr)      * K + k0 + lc);
        float4 a1 = *(const float4*)(A + (size_t)(bm + lr + 64) * K + k0 + lc);
        float4 b0 = *(const float4*)(B + (size_t)(bn + lr)      * K + k0 + lc);
        float4 b1 = *(const float4*)(B + (size_t)(bn + lr + 64) * K + k0 + lc);
        __syncthreads();
        As[lc+0][lr] = a0.x; As[lc+1][lr] = a0.y; As[lc+2][lr] = a0.z; As[lc+3][lr] = a0.w;
        As[lc+0][lr+64] = a1.x; As[lc+1][lr+64] = a1.y; As[lc+2][lr+64] = a1.z; As[lc+3][lr+64] = a1.w;
        Bs[lc+0][lr] = b0.x; Bs[lc+1][lr] = b0.y; Bs[lc+2][lr] = b0.z; Bs[lc+3][lr] = b0.w;
        Bs[lc+0][lr+64] = b1.x; Bs[lc+1][lr+64] = b1.y; Bs[lc+2][lr+64] = b1.z; Bs[lc+3][lr+64] = b1.w;
        __syncthreads();

#pragma unroll
        for (int kk = 0; kk < 16; kk++) {
            float ra[8], rb[8];
            *(float4*)(&ra[0]) = *(const float4*)(&As[kk][ty*4]);
            *(float4*)(&ra[4]) = *(const float4*)(&As[kk][64 + ty*4]);
            *(float4*)(&rb[0]) = *(const float4*)(&Bs[kk][tx*4]);
            *(float4*)(&rb[4]) = *(const float4*)(&Bs[kk][64 + tx*4]);
#pragma unroll
            for (int i = 0; i < 8; i++)
#pragma unroll
                for (int j = 0; j < 8; j++)
                    acc[i][j] += ra[i] * rb[j];
        }
    }

#pragma unroll
    for (int i = 0; i < 8; i++) {
        int m = bm + ((i < 4) ? (ty*4 + i) : (64 + ty*4 + i - 4));
#pragma unroll
        for (int j = 0; j < 8; j++) {
            int n = bn + ((j < 4) ? (tx*4 + j) : (64 + tx*4 + j - 4));
            float v = acc[i][j];
            if (EPI == 0) {
                // plain store, ldc = H_
                Cout[(size_t)m * H_ + n] = v;
            } else {
                // split epilogue for the fused xy GEMM (N = 2R):
                // n < R_  -> g_xr ; n >= R_ -> gelu_exact -> g_gy
                if (n < R_) {
                    g_xr[(size_t)m * R_ + n] = v;
                } else {
                    g_gy[(size_t)m * R_ + (n - R_)] =
                        0.5f * v * (1.0f + erff(v * 0.7071067811865476f));
                }
            }
        }
    }
}

// GEMM1: xy = x @ W_xy^T (N = 2R), split epilogue writes g_xr / g_gy
__global__ __launch_bounds__(256) void gemm_xy(
    const float* __restrict__ x, const float* __restrict__ W_xy)
{
    sgemm_body<1>(x, W_xy, nullptr, H_);
}

// GEMM2: out = g_hg @ W_resid^T (N = H)
__global__ __launch_bounds__(256) void gemm_out(
    const float* __restrict__ W_resid, float* __restrict__ out)
{
    sgemm_body<0>(g_hg, W_resid, out, R_);
}

// ---------------- causal depthwise conv (CW=4) ------------------------------
__global__ void conv_kernel(const float* __restrict__ conv_w,
                            const float* __restrict__ conv_b)
{
    size_t idx = (size_t)blockIdx.x * blockDim.x + threadIdx.x;
    int r = (int)(idx & (R_ - 1));
    size_t row = idx >> 11;            // / R_
    int t = (int)(row & (S_ - 1));
    int b = (int)(row >> 12);          // / S_
    float acc = conv_b[r];
#pragma unroll
    for (int i = 0; i < CW_; i++) {
        int tt = t - (CW_ - 1) + i;
        if (tt >= 0)
            acc += conv_w[i * R_ + r] * g_xr[((size_t)(b * S_ + tt)) * R_ + r];
    }
    g_xc[idx] = acc;
}

// ---------------- block-diag gate GEMMs + gate nonlinearity -----------------
// Per block nb: xg = xc_blk @ ig_w[nb] + ig_b ; ag = xc_blk @ ag_w[nb] + ag_b
// then a = exp(-8*sigmoid(ag)*softplus(a_param)), nx = xc*sigmoid(xg)*sqrt(1-a^2)
__global__ __launch_bounds__(256) void blockdiag_gates(
    const float* __restrict__ igw, const float* __restrict__ igb,
    const float* __restrict__ agw, const float* __restrict__ agb,
    const float* __restrict__ a_param)
{
    __shared__ __align__(16) float Xs[16][128];
    __shared__ __align__(16) float Wi[16][128];
    __shared__ __align__(16) float Wa[16][128];

    const int nb = blockIdx.x;
    const int bm = blockIdx.y * 128;
    const int tid = threadIdx.x;
    const int tx = tid & 15, ty = tid >> 4;
    const int lr = tid >> 2, lc = (tid & 3) << 2;
    const int wr = tid >> 5, wc = (tid & 31) << 2;

    const float* wip = igw + (size_t)nb * BW_ * BW_;
    const float* wap = agw + (size_t)nb * BW_ * BW_;

    float accI[8][8], accA[8][8];
#pragma unroll
    for (int i = 0; i < 8; i++)
#pragma unroll
        for (int j = 0; j < 8; j++) { accI[i][j] = 0.f; accA[i][j] = 0.f; }

    for (int k0 = 0; k0 < BW_; k0 += 16) {
        float4 x0 = *(const float4*)(g_xc + (size_t)(bm + lr)      * R_ + nb*BW_ + k0 + lc);
        float4 x1 = *(const float4*)(g_xc + (size_t)(bm + lr + 64) * R_ + nb*BW_ + k0 + lc);
        float4 wi0 = *(const float4*)(wip + (size_t)(k0 + wr)     * BW_ + wc);
        float4 wi1 = *(const float4*)(wip + (size_t)(k0 + wr + 8) * BW_ + wc);
        float4 wa0 = *(const float4*)(wap + (size_t)(k0 + wr)     * BW_ + wc);
        float4 wa1 = *(const float4*)(wap + (size_t)(k0 + wr + 8) * BW_ + wc);
        __syncthreads();
        Xs[lc+0][lr] = x0.x; Xs[lc+1][lr] = x0.y; Xs[lc+2][lr] = x0.z; Xs[lc+3][lr] = x0.w;
        Xs[lc+0][lr+64] = x1.x; Xs[lc+1][lr+64] = x1.y; Xs[lc+2][lr+64] = x1.z; Xs[lc+3][lr+64] = x1.w;
        *(float4*)(&Wi[wr][wc])     = wi0;
        *(float4*)(&Wi[wr + 8][wc]) = wi1;
        *(float4*)(&Wa[wr][wc])     = wa0;
        *(float4*)(&Wa[wr + 8][wc]) = wa1;
        __syncthreads();

#pragma unroll
        for (int kk = 0; kk < 16; kk++) {
            float ra[8], ri[8], rc[8];
            *(float4*)(&ra[0]) = *(const float4*)(&Xs[kk][ty*4]);
            *(float4*)(&ra[4]) = *(const float4*)(&Xs[kk][64 + ty*4]);
            *(float4*)(&ri[0]) = *(const float4*)(&Wi[kk][tx*4]);
            *(float4*)(&ri[4]) = *(const float4*)(&Wi[kk][64 + tx*4]);
            *(float4*)(&rc[0]) = *(const float4*)(&Wa[kk][tx*4]);
            *(float4*)(&rc[4]) = *(const float4*)(&Wa[kk][64 + tx*4]);
#pragma unroll
            for (int i = 0; i < 8; i++)
#pragma unroll
                for (int j = 0; j < 8; j++) {
                    accI[i][j] += ra[i] * ri[j];
                    accA[i][j] += ra[i] * rc[j];
                }
        }
    }

#pragma unroll
    for (int i = 0; i < 8; i++) {
        int m = bm + ((i < 4) ? (ty*4 + i) : (64 + ty*4 + i - 4));
#pragma unroll
        for (int j = 0; j < 8; j++) {
            int col = (j < 4) ? (tx*4 + j) : (64 + tx*4 + j - 4);
            int r = nb * BW_ + col;
            float xg = accI[i][j] + igb[nb * BW_ + col];
            float ag = accA[i][j] + agb[nb * BW_ + col];
            float ap = a_param[r];
            float sp = (ap > 20.f) ? ap : log1pf(expf(ap));
            float ga = 1.f / (1.f + expf(-ag));
            float la = -8.f * ga * sp;
            float a  = expf(la);
            float mult = sqrtf(-expm1f(2.f * la));
            float gx = 1.f / (1.f + expf(-xg));
            float xv = g_xc[(size_t)m * R_ + r];
            g_av[(size_t)m * R_ + r] = a;
            g_nx[(size_t)m * R_ + r] = xv * gx * mult;
        }
    }
}

// ---------------- chunked linear-recurrence scan ----------------------------
__global__ void scanA()
{
    int r = blockIdx.x * 256 + threadIdx.x;
    int chunk = blockIdx.y;
    int b = blockIdx.z;
    size_t base = ((size_t)(b * S_ + chunk * CHL)) * R_ + r;
    const float* __restrict__ pa = g_av + base;
    const float* __restrict__ px = g_nx + base;
    float A = 1.f, Bv = 0.f;
#pragma unroll 4
    for (int t = 0; t < CHL; t++) {
        float av = pa[(size_t)t * R_];
        float xv = px[(size_t)t * R_];
        Bv = av * Bv + xv;
        A *= av;
    }
    int ch = b * R_ + r;
    g_Asum[ch * NCHUNK + chunk] = A;
    g_Bsum[ch * NCHUNK + chunk] = Bv;
}

__global__ void scanB()
{
    int ch = blockIdx.x * 256 + threadIdx.x;
    float h = 0.f;
#pragma unroll
    for (int c = 0; c < NCHUNK; c++) {
        g_carry[ch * NCHUNK + c] = h;
        h = g_Asum[ch * NCHUNK + c] * h + g_Bsum[ch * NCHUNK + c];
    }
}

__global__ void scanC()
{
    int r = blockIdx.x * 256 + threadIdx.x;
    int chunk = blockIdx.y;
    int b = blockIdx.z;
    size_t base = ((size_t)(b * S_ + chunk * CHL)) * R_ + r;
    const float* __restrict__ pa = g_av + base;
    const float* __restrict__ px = g_nx + base;
    const float* __restrict__ pg = g_gy + base;
    float* __restrict__ po = g_hg + base;
    int ch = b * R_ + r;
    float h = g_carry[ch * NCHUNK + chunk];
#pragma unroll 4
    for (int t = 0; t < CHL; t++) {
        float av = pa[(size_t)t * R_];
        float xv = px[(size_t)t * R_];
        h = av * h + xv;
        po[(size_t)t * R_] = h * pg[(size_t)t * R_];
    }
}

// ---------------- host launcher ---------------------------------------------
// Pure kernel launches only: no cudaGetSymbolAddress, no memcpy, nothing else.
extern "C" void kernel_launch(void* const* d_in, const int* in_sizes, int n_in,
                              void* d_out, int out_size)
{
    const float* x       = (const float*)d_in[0];
    const float* W_xy    = (const float*)d_in[1];
    const float* ig_w    = (const float*)d_in[2];
    const float* ig_b    = (const float*)d_in[3];
    const float* ag_w    = (const float*)d_in[4];
    const float* ag_b    = (const float*)d_in[5];
    const float* a_param = (const float*)d_in[6];
    const float* conv_w  = (const float*)d_in[7];
    const float* conv_b  = (const float*)d_in[8];
    const float* W_resid = (const float*)d_in[9];
    float* out = (float*)d_out;

    // 1) xy = x @ W_xy^T, split into g_xr / gelu -> g_gy
    {
        dim3 grid(2 * R_ / 128, M_ / 128);   // (32, 64)
        gemm_xy<<<grid, 256>>>(x, W_xy);
    }
    // 2) causal depthwise conv
    {
        size_t total = (size_t)M_ * R_;
        conv_kernel<<<(unsigned)(total / 256), 256>>>(conv_w, conv_b);
    }
    // 3) block-diag gates + RG-LRU elementwise
    {
        dim3 grid(NB_, M_ / 128);            // (16, 64)
        blockdiag_gates<<<grid, 256>>>(ig_w, ig_b, ag_w, ag_b, a_param);
    }
    // 4) chunked scan, fused * gelu(y)
    {
        dim3 gA(R_ / 256, NCHUNK, B_);       // (8, 16, 2)
        scanA<<<gA, 256>>>();
        scanB<<<NCH / 256, 256>>>();         // 16 blocks
        scanC<<<gA, 256>>>();
    }
    // 5) out = g_hg @ W_resid^T
    {
        dim3 grid(H_ / 128, M_ / 128);       // (16, 64)
        gemm_out<<<grid, 256>>>(W_resid, out);
    }
}

// round 8
// speedup vs baseline: 2.2807x; 2.2807x over previous
#include <cuda_runtime.h>
#include <cuda_bf16.h>
#include <math.h>
#include <stdint.h>

// ---------------- problem constants ----------------
#define B_  2
#define S_  4096
#define H_  2048
#define R_  2048
#define NB_ 16
#define BW_ 128
#define CW_ 4
#define M_  (B_*S_)        // 8192
#define NCHUNK 16
#define CHL (S_/NCHUNK)    // 256
#define NCH (B_*R_)        // 4096
#define KDIM 2048
#define KC  64             // K elements per SMEM chunk
#define NKC (KDIM/KC)      // 32 chunks

// ---------------- scratch (device globals; no allocations allowed) ----------
__device__ float g_xr[(size_t)M_*R_];
__device__ float g_gy[(size_t)M_*R_];
__device__ float g_xc[(size_t)M_*R_];
__device__ float g_av[(size_t)M_*R_];
__device__ float g_nx[(size_t)M_*R_];
__device__ float g_Asum[NCH*NCHUNK];
__device__ float g_Bsum[NCH*NCHUNK];
__device__ float g_carry[NCH*NCHUNK];

__device__ __nv_bfloat16 g_xh [(size_t)M_*H_];
__device__ __nv_bfloat16 g_xl [(size_t)M_*H_];
__device__ __nv_bfloat16 g_wxyh[(size_t)2*R_*H_];
__device__ __nv_bfloat16 g_wxyl[(size_t)2*R_*H_];
__device__ __nv_bfloat16 g_wrh[(size_t)H_*R_];
__device__ __nv_bfloat16 g_wrl[(size_t)H_*R_];
__device__ __nv_bfloat16 g_hgh[(size_t)M_*R_];
__device__ __nv_bfloat16 g_hgl[(size_t)M_*R_];

// ---------------- helpers ----------------------------------------------------
__device__ __forceinline__ uint32_t smem_to_u32(const void* p) {
    uint32_t a;
    asm("{ .reg .u64 t; cvta.to.shared.u64 t, %1; cvt.u32.u64 %0, t; }"
        : "=r"(a) : "l"(p));
    return a;
}

__device__ __forceinline__ void ldsm4(uint32_t addr,
    uint32_t& r0, uint32_t& r1, uint32_t& r2, uint32_t& r3)
{
    asm volatile("ldmatrix.sync.aligned.m8n8.x4.shared.b16 {%0,%1,%2,%3}, [%4];"
        : "=r"(r0), "=r"(r1), "=r"(r2), "=r"(r3) : "r"(addr));
}

__device__ __forceinline__ void mma16816(float* c,
    const uint32_t* a, uint32_t b0, uint32_t b1)
{
    asm volatile(
        "mma.sync.aligned.m16n8k16.row.col.f32.bf16.bf16.f32 "
        "{%0,%1,%2,%3}, {%4,%5,%6,%7}, {%8,%9}, {%0,%1,%2,%3};"
        : "+f"(c[0]), "+f"(c[1]), "+f"(c[2]), "+f"(c[3])
        : "r"(a[0]), "r"(a[1]), "r"(a[2]), "r"(a[3]), "r"(b0), "r"(b1));
}

__device__ __forceinline__ void split1(float v, __nv_bfloat16& h, __nv_bfloat16& l)
{
    h = __float2bfloat16(v);
    l = __float2bfloat16(v - __bfloat162float(h));
}

// ---------------- fp32 -> (bf16 hi, bf16 lo) split --------------------------
template <int DST>
__global__ void split_kernel(const float4* __restrict__ src)
{
    int i = blockIdx.x * 256 + threadIdx.x;
    float4 v = src[i];
    __nv_bfloat16 h0, h1, h2, h3, l0, l1, l2, l3;
    split1(v.x, h0, l0); split1(v.y, h1, l1);
    split1(v.z, h2, l2); split1(v.w, h3, l3);
    uint2 hv, lv;
    hv.x = (uint32_t)__bfloat16_as_ushort(h0) | ((uint32_t)__bfloat16_as_ushort(h1) << 16);
    hv.y = (uint32_t)__bfloat16_as_ushort(h2) | ((uint32_t)__bfloat16_as_ushort(h3) << 16);
    lv.x = (uint32_t)__bfloat16_as_ushort(l0) | ((uint32_t)__bfloat16_as_ushort(l1) << 16);
    lv.y = (uint32_t)__bfloat16_as_ushort(l2) | ((uint32_t)__bfloat16_as_ushort(l3) << 16);
    __nv_bfloat16 *hp, *lp;
    if (DST == 0)      { hp = g_xh;   lp = g_xl;   }
    else if (DST == 1) { hp = g_wxyh; lp = g_wxyl; }
    else               { hp = g_wrh;  lp = g_wrl;  }
    *(uint2*)(hp + 4ull * i) = hv;
    *(uint2*)(lp + 4ull * i) = lv;
}

// ---------------- HMMA split-bf16 GEMM (TN) ----------------------------------
// C[m,n] = sum_k A[m,k]*B[n,k]; A:[M,2048], B:[N,2048] row-major.
// Tile 128x128, 8 warps (4 x 2), warp tile 32x64. BK=64 double-buffered via
// cp.async. 3-product split: Ah*Bh + Ah*Bl + Al*Bh, fp32 accumulate.
// SMEM stage: Ah | Al | Bh | Bl, each 128 rows x 128 bytes, xor-swizzled.
#define TILEB   16384
#define STAGEB  (4*TILEB)
#define GEMM_SMEM (2*STAGEB)   // 131072

__device__ __forceinline__ void load_tile_async(
    const __nv_bfloat16* __restrict__ g, int row0, int kc,
    uint32_t sdst, int tid)
{
#pragma unroll
    for (int i = 0; i < 4; i++) {
        int u = i * 256 + tid;          // 0..1023 16B units
        int row = u >> 3;               // 0..127
        int un  = u & 7;                // unit within 128B row
        const __nv_bfloat16* src = g + (size_t)(row0 + row) * KDIM + kc * KC + un * 8;
        uint32_t dst = sdst + row * 128 + ((un ^ (row & 7)) * 16);
        asm volatile("cp.async.cg.shared.global [%0], [%1], 16;"
            :: "r"(dst), "l"(src) : "memory");
    }
}

// EPI 1: GEMM1 (A=x, B=W_xy): n<R_ -> g_xr ; n>=R_ -> gelu -> g_gy
// EPI 2: GEMM2 (A=hg, B=W_resid): -> Cout (ldc=H_)
template <int EPI>
__global__ __launch_bounds__(256) void gemm_tc(float* __restrict__ Cout)
{
    extern __shared__ char smem[];
    const uint32_t smem_u = smem_to_u32(smem);
    const int tid  = threadIdx.x;
    const int lane = tid & 31;
    const int wm   = (tid >> 5) & 3;    // warp row 0..3  (32 rows each)
    const int wn   = tid >> 7;          // warp col 0..1  (64 cols each)
    const int bm = blockIdx.y * 128;
    const int bn = blockIdx.x * 128;

    const __nv_bfloat16 *Ah, *Al, *Bh, *Bl;
    if (EPI == 1) { Ah = g_xh;  Al = g_xl;  Bh = g_wxyh; Bl = g_wxyl; }
    else          { Ah = g_hgh; Al = g_hgl; Bh = g_wrh;  Bl = g_wrl;  }

    float acc[2][8][4];
#pragma unroll
    for (int mb = 0; mb < 2; mb++)
#pragma unroll
        for (int n8 = 0; n8 < 8; n8++)
#pragma unroll
            for (int q = 0; q < 4; q++) acc[mb][n8][q] = 0.f;

    // prologue: chunk 0 -> stage 0
    {
        uint32_t sb = smem_u;
        load_tile_async(Ah, bm, 0, sb,             tid);
        load_tile_async(Al, bm, 0, sb + TILEB,     tid);
        load_tile_async(Bh, bn, 0, sb + 2*TILEB,   tid);
        load_tile_async(Bl, bn, 0, sb + 3*TILEB,   tid);
        asm volatile("cp.async.commit_group;" ::: "memory");
    }

    // precomputed lane addressing pieces
    const int a_row = wm * 32 + (lane & 15);          // + mb*16
    const int a_hf  = lane >> 4;                      // k half unit
    const int b_row = wn * 64 + (lane & 7) + ((lane >> 4) << 3);  // + np*16
    const int b_hf  = (lane >> 3) & 1;

    for (int c = 0; c < NKC; c++) {
        if (c + 1 < NKC) {
            uint32_t sb = smem_u + ((c + 1) & 1) * STAGEB;
            load_tile_async(Ah, bm, c + 1, sb,             tid);
            load_tile_async(Al, bm, c + 1, sb + TILEB,     tid);
            load_tile_async(Bh, bn, c + 1, sb + 2*TILEB,   tid);
            load_tile_async(Bl, bn, c + 1, sb + 3*TILEB,   tid);
            asm volatile("cp.async.commit_group;" ::: "memory");
            asm volatile("cp.async.wait_group 1;" ::: "memory");
        } else {
            asm volatile("cp.async.wait_group 0;" ::: "memory");
        }
        __syncthreads();

        const uint32_t sA = smem_u + (c & 1) * STAGEB;
        const uint32_t sB = sA + 2*TILEB;

#pragma unroll
        for (int ks = 0; ks < 4; ks++) {
            uint32_t ah[2][4], al[2][4];
#pragma unroll
            for (int mb = 0; mb < 2; mb++) {
                int row = a_row + mb * 16;
                int un  = ks * 2 + a_hf;
                uint32_t off = row * 128 + ((un ^ (row & 7)) * 16);
                ldsm4(sA + off,         ah[mb][0], ah[mb][1], ah[mb][2], ah[mb][3]);
                ldsm4(sA + TILEB + off, al[mb][0], al[mb][1], al[mb][2], al[mb][3]);
            }
#pragma unroll
            for (int np = 0; np < 4; np++) {
                int row = b_row + np * 16;
                int un  = ks * 2 + b_hf;
                uint32_t off = row * 128 + ((un ^ (row & 7)) * 16);
                uint32_t bh0, bh1, bh2, bh3, bl0, bl1, bl2, bl3;
                ldsm4(sB + off,         bh0, bh1, bh2, bh3);
                ldsm4(sB + TILEB + off, bl0, bl1, bl2, bl3);
#pragma unroll
                for (int mb = 0; mb < 2; mb++) {
                    mma16816(acc[mb][np*2+0], ah[mb], bh0, bh1);
                    mma16816(acc[mb][np*2+1], ah[mb], bh2, bh3);
                    mma16816(acc[mb][np*2+0], ah[mb], bl0, bl1);
                    mma16816(acc[mb][np*2+1], ah[mb], bl2, bl3);
                    mma16816(acc[mb][np*2+0], al[mb], bh0, bh1);
                    mma16816(acc[mb][np*2+1], al[mb], bh2, bh3);
                }
            }
        }
        __syncthreads();
    }

    // ---------------- epilogue ----------------
    const int mrow0 = bm + wm * 32 + (lane >> 2);
    const int ncol0 = bn + wn * 64 + (lane & 3) * 2;
#pragma unroll
    for (int mb = 0; mb < 2; mb++) {
#pragma unroll
        for (int n8 = 0; n8 < 8; n8++) {
            int n = ncol0 + n8 * 8;
            int m0 = mrow0 + mb * 16;
            float2 v0 = make_float2(acc[mb][n8][0], acc[mb][n8][1]);
            float2 v1 = make_float2(acc[mb][n8][2], acc[mb][n8][3]);
            if (EPI == 2) {
                *(float2*)(Cout + (size_t)m0 * H_ + n)       = v0;
                *(float2*)(Cout + (size_t)(m0 + 8) * H_ + n) = v1;
            } else if (bn < R_) {
                *(float2*)(g_xr + (size_t)m0 * R_ + n)       = v0;
                *(float2*)(g_xr + (size_t)(m0 + 8) * R_ + n) = v1;
            } else {
                v0.x = 0.5f * v0.x * (1.0f + erff(v0.x * 0.7071067811865476f));
                v0.y = 0.5f * v0.y * (1.0f + erff(v0.y * 0.7071067811865476f));
                v1.x = 0.5f * v1.x * (1.0f + erff(v1.x * 0.7071067811865476f));
                v1.y = 0.5f * v1.y * (1.0f + erff(v1.y * 0.7071067811865476f));
                *(float2*)(g_gy + (size_t)m0 * R_ + (n - R_))       = v0;
                *(float2*)(g_gy + (size_t)(m0 + 8) * R_ + (n - R_)) = v1;
            }
        }
    }
}

// ---------------- causal depthwise conv (CW=4) ------------------------------
__global__ void conv_kernel(const float* __restrict__ conv_w,
                            const float* __restrict__ conv_b)
{
    size_t idx = (size_t)blockIdx.x * blockDim.x + threadIdx.x;
    int r = (int)(idx & (R_ - 1));
    size_t row = idx >> 11;
    int t = (int)(row & (S_ - 1));
    int b = (int)(row >> 12);
    float acc = conv_b[r];
#pragma unroll
    for (int i = 0; i < CW_; i++) {
        int tt = t - (CW_ - 1) + i;
        if (tt >= 0)
            acc += conv_w[i * R_ + r] * g_xr[((size_t)(b * S_ + tt)) * R_ + r];
    }
    g_xc[idx] = acc;
}

// ---------------- block-diag gate GEMMs + RG-LRU elementwise ----------------
__global__ __launch_bounds__(256) void blockdiag_gates(
    const float* __restrict__ igw, const float* __restrict__ igb,
    const float* __restrict__ agw, const float* __restrict__ agb,
    const float* __restrict__ a_param)
{
    __shared__ __align__(16) float Xs[16][128];
    __shared__ __align__(16) float Wi[16][128];
    __shared__ __align__(16) float Wa[16][128];

    const int nb = blockIdx.x;
    const int bm = blockIdx.y * 128;
    const int tid = threadIdx.x;
    const int tx = tid & 15, ty = tid >> 4;
    const int lr = tid >> 2, lc = (tid & 3) << 2;
    const int wr = tid >> 5, wc = (tid & 31) << 2;

    const float* wip = igw + (size_t)nb * BW_ * BW_;
    const float* wap = agw + (size_t)nb * BW_ * BW_;

    float accI[8][8], accA[8][8];
#pragma unroll
    for (int i = 0; i < 8; i++)
#pragma unroll
        for (int j = 0; j < 8; j++) { accI[i][j] = 0.f; accA[i][j] = 0.f; }

    for (int k0 = 0; k0 < BW_; k0 += 16) {
        float4 x0 = *(const float4*)(g_xc + (size_t)(bm + lr)      * R_ + nb*BW_ + k0 + lc);
        float4 x1 = *(const float4*)(g_xc + (size_t)(bm + lr + 64) * R_ + nb*BW_ + k0 + lc);
        float4 wi0 = *(const float4*)(wip + (size_t)(k0 + wr)     * BW_ + wc);
        float4 wi1 = *(const float4*)(wip + (size_t)(k0 + wr + 8) * BW_ + wc);
        float4 wa0 = *(const float4*)(wap + (size_t)(k0 + wr)     * BW_ + wc);
        float4 wa1 = *(const float4*)(wap + (size_t)(k0 + wr + 8) * BW_ + wc);
        __syncthreads();
        Xs[lc+0][lr] = x0.x; Xs[lc+1][lr] = x0.y; Xs[lc+2][lr] = x0.z; Xs[lc+3][lr] = x0.w;
        Xs[lc+0][lr+64] = x1.x; Xs[lc+1][lr+64] = x1.y; Xs[lc+2][lr+64] = x1.z; Xs[lc+3][lr+64] = x1.w;
        *(float4*)(&Wi[wr][wc])     = wi0;
        *(float4*)(&Wi[wr + 8][wc]) = wi1;
        *(float4*)(&Wa[wr][wc])     = wa0;
        *(float4*)(&Wa[wr + 8][wc]) = wa1;
        __syncthreads();

#pragma unroll
        for (int kk = 0; kk < 16; kk++) {
            float ra[8], ri[8], rc[8];
            *(float4*)(&ra[0]) = *(const float4*)(&Xs[kk][ty*4]);
            *(float4*)(&ra[4]) = *(const float4*)(&Xs[kk][64 + ty*4]);
            *(float4*)(&ri[0]) = *(const float4*)(&Wi[kk][tx*4]);
            *(float4*)(&ri[4]) = *(const float4*)(&Wi[kk][64 + tx*4]);
            *(float4*)(&rc[0]) = *(const float4*)(&Wa[kk][tx*4]);
            *(float4*)(&rc[4]) = *(const float4*)(&Wa[kk][64 + tx*4]);
#pragma unroll
            for (int i = 0; i < 8; i++)
#pragma unroll
                for (int j = 0; j < 8; j++) {
                    accI[i][j] += ra[i] * ri[j];
                    accA[i][j] += ra[i] * rc[j];
                }
        }
    }

#pragma unroll
    for (int i = 0; i < 8; i++) {
        int m = bm + ((i < 4) ? (ty*4 + i) : (64 + ty*4 + i - 4));
#pragma unroll
        for (int j = 0; j < 8; j++) {
            int col = (j < 4) ? (tx*4 + j) : (64 + tx*4 + j - 4);
            int r = nb * BW_ + col;
            float xg = accI[i][j] + igb[nb * BW_ + col];
            float ag = accA[i][j] + agb[nb * BW_ + col];
            float ap = a_param[r];
            float sp = (ap > 20.f) ? ap : log1pf(expf(ap));
            float ga = 1.f / (1.f + expf(-ag));
            float la = -8.f * ga * sp;
            float a  = expf(la);
            float mult = sqrtf(-expm1f(2.f * la));
            float gx = 1.f / (1.f + expf(-xg));
            float xv = g_xc[(size_t)m * R_ + r];
            g_av[(size_t)m * R_ + r] = a;
            g_nx[(size_t)m * R_ + r] = xv * gx * mult;
        }
    }
}

// ---------------- chunked linear-recurrence scan ----------------------------
__global__ void scanA()
{
    int r = blockIdx.x * 256 + threadIdx.x;
    int chunk = blockIdx.y;
    int b = blockIdx.z;
    size_t base = ((size_t)(b * S_ + chunk * CHL)) * R_ + r;
    const float* __restrict__ pa = g_av + base;
    const float* __restrict__ px = g_nx + base;
    float A = 1.f, Bv = 0.f;
#pragma unroll 4
    for (int t = 0; t < CHL; t++) {
        float av = pa[(size_t)t * R_];
        float xv = px[(size_t)t * R_];
        Bv = av * Bv + xv;
        A *= av;
    }
    int ch = b * R_ + r;
    g_Asum[ch * NCHUNK + chunk] = A;
    g_Bsum[ch * NCHUNK + chunk] = Bv;
}

__global__ void scanB()
{
    int ch = blockIdx.x * 256 + threadIdx.x;
    float h = 0.f;
#pragma unroll
    for (int c = 0; c < NCHUNK; c++) {
        g_carry[ch * NCHUNK + c] = h;
        h = g_Asum[ch * NCHUNK + c] * h + g_Bsum[ch * NCHUNK + c];
    }
}

__global__ void scanC()
{
    int r = blockIdx.x * 256 + threadIdx.x;
    int chunk = blockIdx.y;
    int b = blockIdx.z;
    size_t base = ((size_t)(b * S_ + chunk * CHL)) * R_ + r;
    const float* __restrict__ pa = g_av + base;
    const float* __restrict__ px = g_nx + base;
    const float* __restrict__ pg = g_gy + base;
    __nv_bfloat16* __restrict__ ph = g_hgh + base;
    __nv_bfloat16* __restrict__ pl = g_hgl + base;
    int ch = b * R_ + r;
    float h = g_carry[ch * NCHUNK + chunk];
#pragma unroll 4
    for (int t = 0; t < CHL; t++) {
        float av = pa[(size_t)t * R_];
        float xv = px[(size_t)t * R_];
        h = av * h + xv;
        float hg = h * pg[(size_t)t * R_];
        __nv_bfloat16 hh, hl;
        split1(hg, hh, hl);
        ph[(size_t)t * R_] = hh;
        pl[(size_t)t * R_] = hl;
    }
}

// ---------------- host launcher ---------------------------------------------
extern "C" void kernel_launch(void* const* d_in, const int* in_sizes, int n_in,
                              void* d_out, int out_size)
{
    const float* x       = (const float*)d_in[0];
    const float* W_xy    = (const float*)d_in[1];
    const float* ig_w    = (const float*)d_in[2];
    const float* ig_b    = (const float*)d_in[3];
    const float* ag_w    = (const float*)d_in[4];
    const float* ag_b    = (const float*)d_in[5];
    const float* a_param = (const float*)d_in[6];
    const float* conv_w  = (const float*)d_in[7];
    const float* conv_b  = (const float*)d_in[8];
    const float* W_resid = (const float*)d_in[9];
    float* out = (float*)d_out;

    cudaFuncSetAttribute(gemm_tc<1>, cudaFuncAttributeMaxDynamicSharedMemorySize, GEMM_SMEM);
    cudaFuncSetAttribute(gemm_tc<2>, cudaFuncAttributeMaxDynamicSharedMemorySize, GEMM_SMEM);

    // 0) split operands to bf16 hi/lo
    split_kernel<0><<<(M_ * H_ / 4) / 256, 256>>>((const float4*)x);
    split_kernel<1><<<(2 * R_ * H_ / 4) / 256, 256>>>((const float4*)W_xy);
    split_kernel<2><<<(H_ * R_ / 4) / 256, 256>>>((const float4*)W_resid);

    // 1) xy = x @ W_xy^T  (HMMA split-bf16; epilogue -> g_xr, gelu -> g_gy)
    {
        dim3 grid(2 * R_ / 128, M_ / 128);   // (32, 64)
        gemm_tc<1><<<grid, 256, GEMM_SMEM>>>(nullptr);
    }
    // 2) causal depthwise conv
    conv_kernel<<<(unsigned)((size_t)M_ * R_ / 256), 256>>>(conv_w, conv_b);
    // 3) block-diag gates + RG-LRU elementwise
    {
        dim3 grid(NB_, M_ / 128);
        blockdiag_gates<<<grid, 256>>>(ig_w, ig_b, ag_w, ag_b, a_param);
    }
    // 4) chunked scan, fused * gelu(y), bf16-split output
    {
        dim3 gA(R_ / 256, NCHUNK, B_);
        scanA<<<gA, 256>>>();
        scanB<<<NCH / 256, 256>>>();
        scanC<<<gA, 256>>>();
    }
    // 5) out = hg @ W_resid^T  (HMMA split-bf16)
    {
        dim3 grid(H_ / 128, M_ / 128);       // (16, 64)
        gemm_tc<2><<<grid, 256, GEMM_SMEM>>>(out);
    }
}

// round 9
// speedup vs baseline: 2.2830x; 1.0010x over previous
#include <cuda_runtime.h>
#include <cuda_bf16.h>
#include <math.h>
#include <stdint.h>

// ---------------- problem constants ----------------
#define B_  2
#define S_  4096
#define H_  2048
#define R_  2048
#define NB_ 16
#define BW_ 128
#define CW_ 4
#define M_  (B_*S_)        // 8192
#define NCHUNK 16
#define CHL (S_/NCHUNK)    // 256
#define NCH (B_*R_)        // 4096
#define KDIM 2048
#define KC  64             // K elements per SMEM chunk
#define NKC (KDIM/KC)      // 32 chunks

// ---------------- scratch (device globals; no allocations allowed) ----------
__device__ float g_xr[(size_t)M_*R_];
__device__ float g_gy[(size_t)M_*R_];
__device__ float g_xc[(size_t)M_*R_];
__device__ float g_av[(size_t)M_*R_];
__device__ float g_nx[(size_t)M_*R_];
__device__ float g_Asum[NCH*NCHUNK];
__device__ float g_Bsum[NCH*NCHUNK];
__device__ float g_carry[NCH*NCHUNK];

__device__ __nv_bfloat16 g_xh [(size_t)M_*H_];
__device__ __nv_bfloat16 g_xl [(size_t)M_*H_];
__device__ __nv_bfloat16 g_wxyh[(size_t)2*R_*H_];
__device__ __nv_bfloat16 g_wxyl[(size_t)2*R_*H_];
__device__ __nv_bfloat16 g_wrh[(size_t)H_*R_];
__device__ __nv_bfloat16 g_wrl[(size_t)H_*R_];
__device__ __nv_bfloat16 g_hgh[(size_t)M_*R_];
__device__ __nv_bfloat16 g_hgl[(size_t)M_*R_];

// ---------------- helpers ----------------------------------------------------
__device__ __forceinline__ uint32_t smem_to_u32(const void* p) {
    uint32_t a;
    asm("{ .reg .u64 t; cvta.to.shared.u64 t, %1; cvt.u32.u64 %0, t; }"
        : "=r"(a) : "l"(p));
    return a;
}

__device__ __forceinline__ void ldsm4(uint32_t addr,
    uint32_t& r0, uint32_t& r1, uint32_t& r2, uint32_t& r3)
{
    asm volatile("ldmatrix.sync.aligned.m8n8.x4.shared.b16 {%0,%1,%2,%3}, [%4];"
        : "=r"(r0), "=r"(r1), "=r"(r2), "=r"(r3) : "r"(addr));
}

__device__ __forceinline__ void mma16816(float* c,
    const uint32_t* a, uint32_t b0, uint32_t b1)
{
    asm volatile(
        "mma.sync.aligned.m16n8k16.row.col.f32.bf16.bf16.f32 "
        "{%0,%1,%2,%3}, {%4,%5,%6,%7}, {%8,%9}, {%0,%1,%2,%3};"
        : "+f"(c[0]), "+f"(c[1]), "+f"(c[2]), "+f"(c[3])
        : "r"(a[0]), "r"(a[1]), "r"(a[2]), "r"(a[3]), "r"(b0), "r"(b1));
}

__device__ __forceinline__ void split1(float v, __nv_bfloat16& h, __nv_bfloat16& l)
{
    h = __float2bfloat16(v);
    l = __float2bfloat16(v - __bfloat162float(h));
}

// ---------------- fp32 -> (bf16 hi, bf16 lo) split --------------------------
template <int DST>
__global__ void split_kernel(const float4* __restrict__ src)
{
    int i = blockIdx.x * 256 + threadIdx.x;
    float4 v = src[i];
    __nv_bfloat16 h0, h1, h2, h3, l0, l1, l2, l3;
    split1(v.x, h0, l0); split1(v.y, h1, l1);
    split1(v.z, h2, l2); split1(v.w, h3, l3);
    uint2 hv, lv;
    hv.x = (uint32_t)__bfloat16_as_ushort(h0) | ((uint32_t)__bfloat16_as_ushort(h1) << 16);
    hv.y = (uint32_t)__bfloat16_as_ushort(h2) | ((uint32_t)__bfloat16_as_ushort(h3) << 16);
    lv.x = (uint32_t)__bfloat16_as_ushort(l0) | ((uint32_t)__bfloat16_as_ushort(l1) << 16);
    lv.y = (uint32_t)__bfloat16_as_ushort(l2) | ((uint32_t)__bfloat16_as_ushort(l3) << 16);
    __nv_bfloat16 *hp, *lp;
    if (DST == 0)      { hp = g_xh;   lp = g_xl;   }
    else if (DST == 1) { hp = g_wxyh; lp = g_wxyl; }
    else               { hp = g_wrh;  lp = g_wrl;  }
    *(uint2*)(hp + 4ull * i) = hv;
    *(uint2*)(lp + 4ull * i) = lv;
}

// ---------------- HMMA split-bf16 GEMM (TN) ----------------------------------
// C[m,n] = sum_k A[m,k]*B[n,k]; A:[M,2048], B:[N,2048] row-major.
// Tile 128x128, 8 warps (4 x 2), warp tile 32x64. BK=64 double-buffered via
// cp.async. 3-product split: Ah*Bh + Ah*Bl + Al*Bh, fp32 accumulate.
// SMEM stage: Ah | Al | Bh | Bl, each 128 rows x 128 bytes, xor-swizzled.
#define TILEB   16384
#define STAGEB  (4*TILEB)
#define GEMM_SMEM (2*STAGEB)   // 131072

__device__ __forceinline__ void load_tile_async(
    const __nv_bfloat16* __restrict__ g, int row0, int kc,
    uint32_t sdst, int tid)
{
#pragma unroll
    for (int i = 0; i < 4; i++) {
        int u = i * 256 + tid;          // 0..1023 16B units
        int row = u >> 3;               // 0..127
        int un  = u & 7;                // unit within 128B row
        const __nv_bfloat16* src = g + (size_t)(row0 + row) * KDIM + kc * KC + un * 8;
        uint32_t dst = sdst + row * 128 + ((un ^ (row & 7)) * 16);
        asm volatile("cp.async.cg.shared.global [%0], [%1], 16;"
            :: "r"(dst), "l"(src) : "memory");
    }
}

// EPI 1: GEMM1 (A=x, B=W_xy): n<R_ -> g_xr ; n>=R_ -> gelu -> g_gy
// EPI 2: GEMM2 (A=hg, B=W_resid): -> Cout (ldc=H_)
template <int EPI>
__global__ __launch_bounds__(256) void gemm_tc(float* __restrict__ Cout)
{
    extern __shared__ char smem[];
    const uint32_t smem_u = smem_to_u32(smem);
    const int tid  = threadIdx.x;
    const int lane = tid & 31;
    const int wm   = (tid >> 5) & 3;    // warp row 0..3  (32 rows each)
    const int wn   = tid >> 7;          // warp col 0..1  (64 cols each)
    const int bm = blockIdx.y * 128;
    const int bn = blockIdx.x * 128;

    const __nv_bfloat16 *Ah, *Al, *Bh, *Bl;
    if (EPI == 1) { Ah = g_xh;  Al = g_xl;  Bh = g_wxyh; Bl = g_wxyl; }
    else          { Ah = g_hgh; Al = g_hgl; Bh = g_wrh;  Bl = g_wrl;  }

    float acc[2][8][4];
#pragma unroll
    for (int mb = 0; mb < 2; mb++)
#pragma unroll
        for (int n8 = 0; n8 < 8; n8++)
#pragma unroll
            for (int q = 0; q < 4; q++) acc[mb][n8][q] = 0.f;

    // prologue: chunk 0 -> stage 0
    {
        uint32_t sb = smem_u;
        load_tile_async(Ah, bm, 0, sb,             tid);
        load_tile_async(Al, bm, 0, sb + TILEB,     tid);
        load_tile_async(Bh, bn, 0, sb + 2*TILEB,   tid);
        load_tile_async(Bl, bn, 0, sb + 3*TILEB,   tid);
        asm volatile("cp.async.commit_group;" ::: "memory");
    }

    // precomputed lane addressing pieces
    const int a_row = wm * 32 + (lane & 15);          // + mb*16
    const int a_hf  = lane >> 4;                      // k half unit
    const int b_row = wn * 64 + (lane & 7) + ((lane >> 4) << 3);  // + np*16
    const int b_hf  = (lane >> 3) & 1;

    for (int c = 0; c < NKC; c++) {
        if (c + 1 < NKC) {
            uint32_t sb = smem_u + ((c + 1) & 1) * STAGEB;
            load_tile_async(Ah, bm, c + 1, sb,             tid);
            load_tile_async(Al, bm, c + 1, sb + TILEB,     tid);
            load_tile_async(Bh, bn, c + 1, sb + 2*TILEB,   tid);
            load_tile_async(Bl, bn, c + 1, sb + 3*TILEB,   tid);
            asm volatile("cp.async.commit_group;" ::: "memory");
            asm volatile("cp.async.wait_group 1;" ::: "memory");
        } else {
            asm volatile("cp.async.wait_group 0;" ::: "memory");
        }
        __syncthreads();

        const uint32_t sA = smem_u + (c & 1) * STAGEB;
        const uint32_t sB = sA + 2*TILEB;

#pragma unroll
        for (int ks = 0; ks < 4; ks++) {
            uint32_t ah[2][4], al[2][4];
#pragma unroll
            for (int mb = 0; mb < 2; mb++) {
                int row = a_row + mb * 16;
                int un  = ks * 2 + a_hf;
                uint32_t off = row * 128 + ((un ^ (row & 7)) * 16);
                ldsm4(sA + off,         ah[mb][0], ah[mb][1], ah[mb][2], ah[mb][3]);
                ldsm4(sA + TILEB + off, al[mb][0], al[mb][1], al[mb][2], al[mb][3]);
            }
#pragma unroll
            for (int np = 0; np < 4; np++) {
                int row = b_row + np * 16;
                int un  = ks * 2 + b_hf;
                uint32_t off = row * 128 + ((un ^ (row & 7)) * 16);
                uint32_t bh0, bh1, bh2, bh3, bl0, bl1, bl2, bl3;
                ldsm4(sB + off,         bh0, bh1, bh2, bh3);
                ldsm4(sB + TILEB + off, bl0, bl1, bl2, bl3);
#pragma unroll
                for (int mb = 0; mb < 2; mb++) {
                    mma16816(acc[mb][np*2+0], ah[mb], bh0, bh1);
                    mma16816(acc[mb][np*2+1], ah[mb], bh2, bh3);
                    mma16816(acc[mb][np*2+0], ah[mb], bl0, bl1);
                    mma16816(acc[mb][np*2+1], ah[mb], bl2, bl3);
                    mma16816(acc[mb][np*2+0], al[mb], bh0, bh1);
                    mma16816(acc[mb][np*2+1], al[mb], bh2, bh3);
                }
            }
        }
        __syncthreads();
    }

    // ---------------- epilogue ----------------
    const int mrow0 = bm + wm * 32 + (lane >> 2);
    const int ncol0 = bn + wn * 64 + (lane & 3) * 2;
#pragma unroll
    for (int mb = 0; mb < 2; mb++) {
#pragma unroll
        for (int n8 = 0; n8 < 8; n8++) {
            int n = ncol0 + n8 * 8;
            int m0 = mrow0 + mb * 16;
            float2 v0 = make_float2(acc[mb][n8][0], acc[mb][n8][1]);
            float2 v1 = make_float2(acc[mb][n8][2], acc[mb][n8][3]);
            if (EPI == 2) {
                *(float2*)(Cout + (size_t)m0 * H_ + n)       = v0;
                *(float2*)(Cout + (size_t)(m0 + 8) * H_ + n) = v1;
            } else if (bn < R_) {
                *(float2*)(g_xr + (size_t)m0 * R_ + n)       = v0;
                *(float2*)(g_xr + (size_t)(m0 + 8) * R_ + n) = v1;
            } else {
                v0.x = 0.5f * v0.x * (1.0f + erff(v0.x * 0.7071067811865476f));
                v0.y = 0.5f * v0.y * (1.0f + erff(v0.y * 0.7071067811865476f));
                v1.x = 0.5f * v1.x * (1.0f + erff(v1.x * 0.7071067811865476f));
                v1.y = 0.5f * v1.y * (1.0f + erff(v1.y * 0.7071067811865476f));
                *(float2*)(g_gy + (size_t)m0 * R_ + (n - R_))       = v0;
                *(float2*)(g_gy + (size_t)(m0 + 8) * R_ + (n - R_)) = v1;
            }
        }
    }
}

// ---------------- causal depthwise conv (CW=4) ------------------------------
__global__ void conv_kernel(const float* __restrict__ conv_w,
                            const float* __restrict__ conv_b)
{
    size_t idx = (size_t)blockIdx.x * blockDim.x + threadIdx.x;
    int r = (int)(idx & (R_ - 1));
    size_t row = idx >> 11;
    int t = (int)(row & (S_ - 1));
    int b = (int)(row >> 12);
    float acc = conv_b[r];
#pragma unroll
    for (int i = 0; i < CW_; i++) {
        int tt = t - (CW_ - 1) + i;
        if (tt >= 0)
            acc += conv_w[i * R_ + r] * g_xr[((size_t)(b * S_ + tt)) * R_ + r];
    }
    g_xc[idx] = acc;
}

// ---------------- block-diag gate GEMMs + RG-LRU elementwise ----------------
__global__ __launch_bounds__(256) void blockdiag_gates(
    const float* __restrict__ igw, const float* __restrict__ igb,
    const float* __restrict__ agw, const float* __restrict__ agb,
    const float* __restrict__ a_param)
{
    __shared__ __align__(16) float Xs[16][128];
    __shared__ __align__(16) float Wi[16][128];
    __shared__ __align__(16) float Wa[16][128];

    const int nb = blockIdx.x;
    const int bm = blockIdx.y * 128;
    const int tid = threadIdx.x;
    const int tx = tid & 15, ty = tid >> 4;
    const int lr = tid >> 2, lc = (tid & 3) << 2;
    const int wr = tid >> 5, wc = (tid & 31) << 2;

    const float* wip = igw + (size_t)nb * BW_ * BW_;
    const float* wap = agw + (size_t)nb * BW_ * BW_;

    float accI[8][8], accA[8][8];
#pragma unroll
    for (int i = 0; i < 8; i++)
#pragma unroll
        for (int j = 0; j < 8; j++) { accI[i][j] = 0.f; accA[i][j] = 0.f; }

    for (int k0 = 0; k0 < BW_; k0 += 16) {
        float4 x0 = *(const float4*)(g_xc + (size_t)(bm + lr)      * R_ + nb*BW_ + k0 + lc);
        float4 x1 = *(const float4*)(g_xc + (size_t)(bm + lr + 64) * R_ + nb*BW_ + k0 + lc);
        float4 wi0 = *(const float4*)(wip + (size_t)(k0 + wr)     * BW_ + wc);
        float4 wi1 = *(const float4*)(wip + (size_t)(k0 + wr + 8) * BW_ + wc);
        float4 wa0 = *(const float4*)(wap + (size_t)(k0 + wr)     * BW_ + wc);
        float4 wa1 = *(const float4*)(wap + (size_t)(k0 + wr + 8) * BW_ + wc);
        __syncthreads();
        Xs[lc+0][lr] = x0.x; Xs[lc+1][lr] = x0.y; Xs[lc+2][lr] = x0.z; Xs[lc+3][lr] = x0.w;
        Xs[lc+0][lr+64] = x1.x; Xs[lc+1][lr+64] = x1.y; Xs[lc+2][lr+64] = x1.z; Xs[lc+3][lr+64] = x1.w;
        *(float4*)(&Wi[wr][wc])     = wi0;
        *(float4*)(&Wi[wr + 8][wc]) = wi1;
        *(float4*)(&Wa[wr][wc])     = wa0;
        *(float4*)(&Wa[wr + 8][wc]) = wa1;
        __syncthreads();

#pragma unroll
        for (int kk = 0; kk < 16; kk++) {
            float ra[8], ri[8], rc[8];
            *(float4*)(&ra[0]) = *(const float4*)(&Xs[kk][ty*4]);
            *(float4*)(&ra[4]) = *(const float4*)(&Xs[kk][64 + ty*4]);
            *(float4*)(&ri[0]) = *(const float4*)(&Wi[kk][tx*4]);
            *(float4*)(&ri[4]) = *(const float4*)(&Wi[kk][64 + tx*4]);
            *(float4*)(&rc[0]) = *(const float4*)(&Wa[kk][tx*4]);
            *(float4*)(&rc[4]) = *(const float4*)(&Wa[kk][64 + tx*4]);
#pragma unroll
            for (int i = 0; i < 8; i++)
#pragma unroll
                for (int j = 0; j < 8; j++) {
                    accI[i][j] += ra[i] * ri[j];
                    accA[i][j] += ra[i] * rc[j];
                }
        }
    }

#pragma unroll
    for (int i = 0; i < 8; i++) {
        int m = bm + ((i < 4) ? (ty*4 + i) : (64 + ty*4 + i - 4));
#pragma unroll
        for (int j = 0; j < 8; j++) {
            int col = (j < 4) ? (tx*4 + j) : (64 + tx*4 + j - 4);
            int r = nb * BW_ + col;
            float xg = accI[i][j] + igb[nb * BW_ + col];
            float ag = accA[i][j] + agb[nb * BW_ + col];
            float ap = a_param[r];
            float sp = (ap > 20.f) ? ap : log1pf(expf(ap));
            float ga = 1.f / (1.f + expf(-ag));
            float la = -8.f * ga * sp;
            float a  = expf(la);
            float mult = sqrtf(-expm1f(2.f * la));
            float gx = 1.f / (1.f + expf(-xg));
            float xv = g_xc[(size_t)m * R_ + r];
            g_av[(size_t)m * R_ + r] = a;
            g_nx[(size_t)m * R_ + r] = xv * gx * mult;
        }
    }
}

// ---------------- chunked linear-recurrence scan ----------------------------
__global__ void scanA()
{
    int r = blockIdx.x * 256 + threadIdx.x;
    int chunk = blockIdx.y;
    int b = blockIdx.z;
    size_t base = ((size_t)(b * S_ + chunk * CHL)) * R_ + r;
    const float* __restrict__ pa = g_av + base;
    const float* __restrict__ px = g_nx + base;
    float A = 1.f, Bv = 0.f;
#pragma unroll 4
    for (int t = 0; t < CHL; t++) {
        float av = pa[(size_t)t * R_];
        float xv = px[(size_t)t * R_];
        Bv = av * Bv + xv;
        A *= av;
    }
    int ch = b * R_ + r;
    g_Asum[ch * NCHUNK + chunk] = A;
    g_Bsum[ch * NCHUNK + chunk] = Bv;
}

__global__ void scanB()
{
    int ch = blockIdx.x * 256 + threadIdx.x;
    float h = 0.f;
#pragma unroll
    for (int c = 0; c < NCHUNK; c++) {
        g_carry[ch * NCHUNK + c] = h;
        h = g_Asum[ch * NCHUNK + c] * h + g_Bsum[ch * NCHUNK + c];
    }
}

__global__ void scanC()
{
    int r = blockIdx.x * 256 + threadIdx.x;
    int chunk = blockIdx.y;
    int b = blockIdx.z;
    size_t base = ((size_t)(b * S_ + chunk * CHL)) * R_ + r;
    const float* __restrict__ pa = g_av + base;
    const float* __restrict__ px = g_nx + base;
    const float* __restrict__ pg = g_gy + base;
    __nv_bfloat16* __restrict__ ph = g_hgh + base;
    __nv_bfloat16* __restrict__ pl = g_hgl + base;
    int ch = b * R_ + r;
    float h = g_carry[ch * NCHUNK + chunk];
#pragma unroll 4
    for (int t = 0; t < CHL; t++) {
        float av = pa[(size_t)t * R_];
        float xv = px[(size_t)t * R_];
        h = av * h + xv;
        float hg = h * pg[(size_t)t * R_];
        __nv_bfloat16 hh, hl;
        split1(hg, hh, hl);
        ph[(size_t)t * R_] = hh;
        pl[(size_t)t * R_] = hl;
    }
}

// ---------------- host launcher ---------------------------------------------
extern "C" void kernel_launch(void* const* d_in, const int* in_sizes, int n_in,
                              void* d_out, int out_size)
{
    const float* x       = (const float*)d_in[0];
    const float* W_xy    = (const float*)d_in[1];
    const float* ig_w    = (const float*)d_in[2];
    const float* ig_b    = (const float*)d_in[3];
    const float* ag_w    = (const float*)d_in[4];
    const float* ag_b    = (const float*)d_in[5];
    const float* a_param = (const float*)d_in[6];
    const float* conv_w  = (const float*)d_in[7];
    const float* conv_b  = (const float*)d_in[8];
    const float* W_resid = (const float*)d_in[9];
    float* out = (float*)d_out;

    cudaFuncSetAttribute(gemm_tc<1>, cudaFuncAttributeMaxDynamicSharedMemorySize, GEMM_SMEM);
    cudaFuncSetAttribute(gemm_tc<2>, cudaFuncAttributeMaxDynamicSharedMemorySize, GEMM_SMEM);

    // 0) split operands to bf16 hi/lo
    split_kernel<0><<<(M_ * H_ / 4) / 256, 256>>>((const float4*)x);
    split_kernel<1><<<(2 * R_ * H_ / 4) / 256, 256>>>((const float4*)W_xy);
    split_kernel<2><<<(H_ * R_ / 4) / 256, 256>>>((const float4*)W_resid);

    // 1) xy = x @ W_xy^T  (HMMA split-bf16; epilogue -> g_xr, gelu -> g_gy)
    {
        dim3 grid(2 * R_ / 128, M_ / 128);   // (32, 64)
        gemm_tc<1><<<grid, 256, GEMM_SMEM>>>(nullptr);
    }
    // 2) causal depthwise conv
    conv_kernel<<<(unsigned)((size_t)M_ * R_ / 256), 256>>>(conv_w, conv_b);
    // 3) block-diag gates + RG-LRU elementwise
    {
        dim3 grid(NB_, M_ / 128);
        blockdiag_gates<<<grid, 256>>>(ig_w, ig_b, ag_w, ag_b, a_param);
    }
    // 4) chunked scan, fused * gelu(y), bf16-split output
    {
        dim3 gA(R_ / 256, NCHUNK, B_);
        scanA<<<gA, 256>>>();
        scanB<<<NCH / 256, 256>>>();
        scanC<<<gA, 256>>>();
    }
    // 5) out = hg @ W_resid^T  (HMMA split-bf16)
    {
        dim3 grid(H_ / 128, M_ / 128);       // (16, 64)
        gemm_tc<2><<<grid, 256, GEMM_SMEM>>>(out);
    }
}